// round 12
// baseline (speedup 1.0000x reference)
#include <cuda_runtime.h>
#include <cuda_bf16.h>
#include <math.h>
#include <stdint.h>

#define BB   2
#define NN_  4096
#define DD   640
#define HH   8
#define DH   80
#define CN_  77
#define CDIM 768
#define FF_  2560
#define EPS_ 1e-5f
#define SCALE_ATTN 0.11180339887498948f

// ---------------- device scratch (static; no cudaMalloc) -------------------
__device__ float g_x   [(size_t)BB * NN_ * DD];
__device__ float g_h   [(size_t)BB * NN_ * DD];
__device__ float g_q   [(size_t)BB * NN_ * DD];
__device__ float g_k   [(size_t)BB * NN_ * DD];
__device__ float g_v   [(size_t)BB * NN_ * DD];
__device__ float g_attn[(size_t)BB * NN_ * DD];
__device__ float g_proj[(size_t)BB * NN_ * 2 * FF_];
__device__ float g_ffh [(size_t)BB * NN_ * FF_];
__device__ __nv_bfloat16 g_qb[(size_t)BB * NN_ * DD];
__device__ __nv_bfloat16 g_kb[(size_t)BB * NN_ * DD];
__device__ __nv_bfloat16 g_vb[(size_t)BB * NN_ * DD];

// ---------------- helpers ---------------------------------------------------
__device__ __forceinline__ void mma_tf32(float* c, const uint32_t* a, const uint32_t* b) {
    asm volatile(
        "mma.sync.aligned.m16n8k8.row.col.f32.tf32.tf32.f32 "
        "{%0,%1,%2,%3}, {%4,%5,%6,%7}, {%8,%9}, {%0,%1,%2,%3};\n"
        : "+f"(c[0]), "+f"(c[1]), "+f"(c[2]), "+f"(c[3])
        : "r"(a[0]), "r"(a[1]), "r"(a[2]), "r"(a[3]), "r"(b[0]), "r"(b[1]));
}
__device__ __forceinline__ void mma_bf16(float* c, const uint32_t* a, const uint32_t* b) {
    asm volatile(
        "mma.sync.aligned.m16n8k16.row.col.f32.bf16.bf16.f32 "
        "{%0,%1,%2,%3}, {%4,%5,%6,%7}, {%8,%9}, {%0,%1,%2,%3};\n"
        : "+f"(c[0]), "+f"(c[1]), "+f"(c[2]), "+f"(c[3])
        : "r"(a[0]), "r"(a[1]), "r"(a[2]), "r"(a[3]), "r"(b[0]), "r"(b[1]));
}
__device__ __forceinline__ uint32_t packbf(float lo, float hi) {
    uint32_t d;
    asm("cvt.rn.bf16x2.f32 %0, %1, %2;" : "=r"(d) : "f"(hi), "f"(lo));
    return d;
}
__device__ __forceinline__ void cp16(uint32_t s, const void* g) {
    asm volatile("cp.async.ca.shared.global [%0], [%1], 16;\n" :: "r"(s), "l"(g));
}
__device__ __forceinline__ void cp16z(uint32_t s, const void* g, bool valid) {
    int sz = valid ? 16 : 0;
    asm volatile("cp.async.ca.shared.global [%0], [%1], 16, %2;\n"
                 :: "r"(s), "l"(g), "r"(sz));
}
__device__ __forceinline__ void ldsm_x4(uint32_t& r0, uint32_t& r1, uint32_t& r2,
                                        uint32_t& r3, uint32_t sa) {
    asm volatile("ldmatrix.sync.aligned.m8n8.x4.shared.b16 {%0,%1,%2,%3}, [%4];"
                 : "=r"(r0), "=r"(r1), "=r"(r2), "=r"(r3) : "r"(sa));
}
__device__ __forceinline__ void ldsm_x4_t(uint32_t& r0, uint32_t& r1, uint32_t& r2,
                                          uint32_t& r3, uint32_t sa) {
    asm volatile("ldmatrix.sync.aligned.m8n8.x4.trans.shared.b16 {%0,%1,%2,%3}, [%4];"
                 : "=r"(r0), "=r"(r1), "=r"(r2), "=r"(r3) : "r"(sa));
}

// ---------------------------------------------------------------------------
// TF32 mma.sync GEMM; A-fragments via ldmatrix.x4.
// ---------------------------------------------------------------------------
#define AST 20

template<int WN, bool OB>
__global__ __launch_bounds__(256, (WN == 32) ? 2 : 1)
void gemm_mma_k(const float* __restrict__ A, const float* __restrict__ B,
                void* __restrict__ Cv,
                int M, int N, int K, int lda, int ldb, int ldc,
                const float* __restrict__ bias,
                const float* __restrict__ resid)
{
    constexpr int BN  = 4 * WN;
    constexpr int BST = BN + 4;
    constexpr int NF  = WN / 8;
    extern __shared__ uint32_t dsm[];
    uint32_t* const Bsb = dsm + 2 * 128 * AST;

    const int tid  = threadIdx.x;
    const int wid  = tid >> 5;
    const int lane = tid & 31;
    const int g    = lane >> 2;
    const int tg   = lane & 3;
    const int wm   = wid & 1;
    const int wn   = wid >> 1;
    const int m0   = blockIdx.y * 128;
    const int n0   = blockIdx.x * BN;

    // ldmatrix lane addressing for A fragments
    const int arow = lane & 15;
    const int acol = (lane >> 4) * 4;

    const int am = tid >> 2;
    const int ac = (tid & 3) * 4;
    const bool av0 = (m0 + am      < M);
    const bool av1 = (m0 + am + 64 < M);
    const long aoff0 = (long)(av0 ? m0 + am      : 0) * lda;
    const long aoff1 = (long)(av1 ? m0 + am + 64 : 0) * lda;

    const uint32_t asb = (uint32_t)__cvta_generic_to_shared(dsm);
    const uint32_t bsb = (uint32_t)__cvta_generic_to_shared(Bsb);
    constexpr int BCH = (16 * BN / 4) / 256;

    #define GM_ISSUE(k0, buf)                                                         \
    {                                                                                  \
        cp16z(asb + (uint32_t)((buf) * 128 * AST + am * AST + ac) * 4u,                \
              A + aoff0 + (k0) + ac, av0);                                             \
        cp16z(asb + (uint32_t)((buf) * 128 * AST + (am + 64) * AST + ac) * 4u,         \
              A + aoff1 + (k0) + ac, av1);                                             \
        _Pragma("unroll")                                                              \
        for (int i = 0; i < BCH; i++) {                                                \
            const int idx = i * 256 + tid;                                             \
            const int row = idx / (BN / 4);                                            \
            const int col = (idx % (BN / 4)) * 4;                                      \
            cp16(bsb + (uint32_t)((buf) * 16 * BST + row * BST + col) * 4u,            \
                 B + (long)((k0) + row) * ldb + n0 + col);                             \
        }                                                                              \
        asm volatile("cp.async.commit_group;\n" ::);                                   \
    }

    float acc[4][NF][4];
    #pragma unroll
    for (int i = 0; i < 4; i++)
        #pragma unroll
        for (int j = 0; j < NF; j++)
            #pragma unroll
            for (int q = 0; q < 4; q++) acc[i][j][q] = 0.f;

    const int NT = K / 16;
    GM_ISSUE(0, 0);

    for (int kt = 0; kt < NT; kt++) {
        const int buf = kt & 1;
        __syncthreads();
        if (kt + 1 < NT) {
            GM_ISSUE((kt + 1) * 16, buf ^ 1);
            asm volatile("cp.async.wait_group 1;\n" ::);
        } else {
            asm volatile("cp.async.wait_group 0;\n" ::);
        }
        __syncthreads();

        const uint32_t abase = asb + (uint32_t)(buf * 128 * AST) * 4u;
        const uint32_t* Bb = Bsb + buf * 16 * BST;

        #pragma unroll
        for (int kk = 0; kk < 16; kk += 8) {
            uint32_t af[4][4], bf[NF][2];
            #pragma unroll
            for (int mf = 0; mf < 4; mf++) {
                const uint32_t sa = abase +
                    (uint32_t)(((wm * 64 + mf * 16 + arow) * AST + kk + acol) * 4);
                ldsm_x4(af[mf][0], af[mf][1], af[mf][2], af[mf][3], sa);
            }
            #pragma unroll
            for (int nf = 0; nf < NF; nf++) {
                const int cb = wn * WN + nf * 8 + g;
                bf[nf][0] = Bb[(kk + tg)     * BST + cb];
                bf[nf][1] = Bb[(kk + tg + 4) * BST + cb];
            }
            #pragma unroll
            for (int mf = 0; mf < 4; mf++)
                #pragma unroll
                for (int nf = 0; nf < NF; nf++)
                    mma_tf32(acc[mf][nf], af[mf], bf[nf]);
        }
    }

    #pragma unroll
    for (int mf = 0; mf < 4; mf++) {
        const int r0 = m0 + wm * 64 + mf * 16 + g;
        const int r1 = r0 + 8;
        #pragma unroll
        for (int nf = 0; nf < NF; nf++) {
            const int cc = n0 + wn * WN + nf * 8 + tg * 2;
            float b0 = 0.f, b1 = 0.f;
            if (bias) { b0 = bias[cc]; b1 = bias[cc + 1]; }
            if (r0 < M) {
                float v0 = acc[mf][nf][0] + b0;
                float v1 = acc[mf][nf][1] + b1;
                if (resid) {
                    v0 += resid[(long)r0 * ldc + cc];
                    v1 += resid[(long)r0 * ldc + cc + 1];
                }
                if (OB) *(uint32_t*)((__nv_bfloat16*)Cv + (long)r0 * ldc + cc) = packbf(v0, v1);
                else    *(float2*)((float*)Cv + (long)r0 * ldc + cc) = make_float2(v0, v1);
            }
            if (r1 < M) {
                float v0 = acc[mf][nf][2] + b0;
                float v1 = acc[mf][nf][3] + b1;
                if (resid) {
                    v0 += resid[(long)r1 * ldc + cc];
                    v1 += resid[(long)r1 * ldc + cc + 1];
                }
                if (OB) *(uint32_t*)((__nv_bfloat16*)Cv + (long)r1 * ldc + cc) = packbf(v0, v1);
                else    *(float2*)((float*)Cv + (long)r1 * ldc + cc) = make_float2(v0, v1);
            }
        }
    }
}

#define GSM64 ((2 * 128 * AST + 2 * 16 * (256 + 4)) * 4)
#define GSM32 ((2 * 128 * AST + 2 * 16 * (128 + 4)) * 4)

// ---------------------------------------------------------------------------
// bf16 flash attention; K/V fragments via ldmatrix.x4.
// ---------------------------------------------------------------------------
#define FKST 88
#define FBUF 11264
#define FSM  45056

__global__ void __launch_bounds__(256, 2)
flash_bf_k(const __nv_bfloat16* __restrict__ Q, const __nv_bfloat16* __restrict__ K,
           const __nv_bfloat16* __restrict__ V, float* __restrict__ O)
{
    extern __shared__ char fsmc[];
    const uint32_t sb = (uint32_t)__cvta_generic_to_shared(fsmc);

    const int tid  = threadIdx.x;
    const int wid  = tid >> 5;
    const int lane = tid & 31;
    const int g    = lane >> 2;
    const int tg   = lane & 3;
    const int bh   = blockIdx.y;
    const int b    = bh / HH, h = bh % HH;
    const int row0 = blockIdx.x * 128;
    const int NT   = NN_ / 64;

    const __nv_bfloat16* Qp = Q + (long)(b * NN_ + row0) * DD + h * DH;
    const __nv_bfloat16* Kp = K + (long)b * NN_ * DD + h * DH;
    const __nv_bfloat16* Vp = V + (long)b * NN_ * DD + h * DH;
    float* Op = O + (long)(b * NN_ + row0) * DD + h * DH;

    // ldmatrix lane addressing
    const int krow = (lane & 7) + ((lane >> 4) << 3);   // QK non-trans
    const int kseg = ((lane >> 3) & 1) * 16;
    const int vrow = lane & 15;                          // PV trans
    const int vseg = lane >> 4;

    // ---- persistent Q fragments ----
    uint32_t qa[5][4];
    {
        const __nv_bfloat16* q0 = Qp + (long)(wid * 16 + g) * DD;
        const __nv_bfloat16* q1 = q0 + 8 * DD;
        #pragma unroll
        for (int kc = 0; kc < 5; kc++) {
            const int c = kc * 16 + 2 * tg;
            qa[kc][0] = *(const uint32_t*)(q0 + c);
            qa[kc][1] = *(const uint32_t*)(q1 + c);
            qa[kc][2] = *(const uint32_t*)(q0 + c + 8);
            qa[kc][3] = *(const uint32_t*)(q1 + c + 8);
        }
    }

    float oa[10][4];
    #pragma unroll
    for (int nf = 0; nf < 10; nf++)
        #pragma unroll
        for (int q = 0; q < 4; q++) oa[nf][q] = 0.f;
    float mr0 = -1e30f, mr1 = -1e30f, lr0 = 0.f, lr1 = 0.f;

    #define FB_ISSUE(kt, buf)                                                          \
    {                                                                                   \
        for (int i = tid; i < 640; i += 256) {                                          \
            const int r = i / 10, c = i % 10;                                           \
            cp16(sb + (uint32_t)((buf) * FBUF + r * (FKST * 2) + c * 16),               \
                 Kp + (long)((kt) * 64 + r) * DD + c * 8);                              \
        }                                                                               \
        for (int i = tid; i < 640; i += 256) {                                          \
            const int r = i / 10, c = i % 10;                                           \
            cp16(sb + (uint32_t)(2 * FBUF + (buf) * FBUF + r * (FKST * 2) + c * 16),    \
                 Vp + (long)((kt) * 64 + r) * DD + c * 8);                              \
        }                                                                               \
        asm volatile("cp.async.commit_group;\n" ::);                                    \
    }

    FB_ISSUE(0, 0);

    for (int kt = 0; kt < NT; kt++) {
        const int buf = kt & 1;
        __syncthreads();
        if (kt + 1 < NT) {
            FB_ISSUE(kt + 1, buf ^ 1);
            asm volatile("cp.async.wait_group 1;\n" ::);
        } else {
            asm volatile("cp.async.wait_group 0;\n" ::);
        }
        __syncthreads();

        const uint32_t kbase = sb + buf * FBUF;
        const uint32_t vbase = sb + 2 * FBUF + buf * FBUF;

        // ---- S = Q K^T ----
        float sa[8][4];
        #pragma unroll
        for (int nf = 0; nf < 8; nf++)
            #pragma unroll
            for (int q = 0; q < 4; q++) sa[nf][q] = 0.f;

        #pragma unroll
        for (int kc = 0; kc < 5; kc++) {
            #pragma unroll
            for (int nfp = 0; nfp < 4; nfp++) {
                uint32_t b0, b1, b2, b3;
                ldsm_x4(b0, b1, b2, b3,
                        kbase + (uint32_t)((nfp * 16 + krow) * (FKST * 2) + kc * 32 + kseg));
                uint32_t ba[2] = {b0, b1};
                uint32_t bb[2] = {b2, b3};
                mma_bf16(sa[2 * nfp],     qa[kc], ba);
                mma_bf16(sa[2 * nfp + 1], qa[kc], bb);
            }
        }

        // ---- online softmax; P stays in registers ----
        float rm0 = -1e30f, rm1 = -1e30f;
        #pragma unroll
        for (int nf = 0; nf < 8; nf++) {
            rm0 = fmaxf(rm0, fmaxf(sa[nf][0], sa[nf][1]));
            rm1 = fmaxf(rm1, fmaxf(sa[nf][2], sa[nf][3]));
        }
        rm0 *= SCALE_ATTN; rm1 *= SCALE_ATTN;
        rm0 = fmaxf(rm0, __shfl_xor_sync(0xffffffffu, rm0, 1));
        rm0 = fmaxf(rm0, __shfl_xor_sync(0xffffffffu, rm0, 2));
        rm1 = fmaxf(rm1, __shfl_xor_sync(0xffffffffu, rm1, 1));
        rm1 = fmaxf(rm1, __shfl_xor_sync(0xffffffffu, rm1, 2));

        const float mn0 = fmaxf(mr0, rm0);
        const float mn1 = fmaxf(mr1, rm1);
        const float cr0 = __expf(mr0 - mn0);
        const float cr1 = __expf(mr1 - mn1);

        uint32_t pa[4][4];
        float rs0 = 0.f, rs1 = 0.f;
        #pragma unroll
        for (int nf = 0; nf < 8; nf++) {
            float p00 = __expf(sa[nf][0] * SCALE_ATTN - mn0);
            float p01 = __expf(sa[nf][1] * SCALE_ATTN - mn0);
            float p10 = __expf(sa[nf][2] * SCALE_ATTN - mn1);
            float p11 = __expf(sa[nf][3] * SCALE_ATTN - mn1);
            rs0 += p00 + p01;
            rs1 += p10 + p11;
            const int kc = nf >> 1, hi = (nf & 1) ? 2 : 0;
            pa[kc][hi]     = packbf(p00, p01);
            pa[kc][hi + 1] = packbf(p10, p11);
        }
        rs0 += __shfl_xor_sync(0xffffffffu, rs0, 1);
        rs0 += __shfl_xor_sync(0xffffffffu, rs0, 2);
        rs1 += __shfl_xor_sync(0xffffffffu, rs1, 1);
        rs1 += __shfl_xor_sync(0xffffffffu, rs1, 2);

        lr0 = lr0 * cr0 + rs0;  mr0 = mn0;
        lr1 = lr1 * cr1 + rs1;  mr1 = mn1;

        #pragma unroll
        for (int nf = 0; nf < 10; nf++) {
            oa[nf][0] *= cr0; oa[nf][1] *= cr0;
            oa[nf][2] *= cr1; oa[nf][3] *= cr1;
        }

        // ---- O += P V ----
        #pragma unroll
        for (int kc = 0; kc < 4; kc++) {
            #pragma unroll
            for (int nfp = 0; nfp < 5; nfp++) {
                uint32_t b0, b1, b2, b3;
                ldsm_x4_t(b0, b1, b2, b3,
                          vbase + (uint32_t)((kc * 16 + vrow) * (FKST * 2)
                                             + (nfp * 2 + vseg) * 16));
                uint32_t ba[2] = {b0, b1};
                uint32_t bb[2] = {b2, b3};
                mma_bf16(oa[2 * nfp],     pa[kc], ba);
                mma_bf16(oa[2 * nfp + 1], pa[kc], bb);
            }
        }
    }

    const float inv0 = 1.f / lr0;
    const float inv1 = 1.f / lr1;
    #pragma unroll
    for (int nf = 0; nf < 10; nf++) {
        const int cc = nf * 8 + tg * 2;
        *(float2*)(Op + (long)(wid * 16 + g)     * DD + cc) =
            make_float2(oa[nf][0] * inv0, oa[nf][1] * inv0);
        *(float2*)(Op + (long)(wid * 16 + g + 8) * DD + cc) =
            make_float2(oa[nf][2] * inv1, oa[nf][3] * inv1);
    }
}

// ---------------- LayerNorm (warp per row) ----------------------------------
__global__ __launch_bounds__(256)
void ln_k(const float* __restrict__ x, const float* __restrict__ w,
          const float* __restrict__ b, float* __restrict__ out)
{
    const int lane = threadIdx.x & 31;
    const long row = (long)blockIdx.x * 8 + (threadIdx.x >> 5);
    const float4* p = (const float4*)(x + row * DD);

    float4 v[5];
    float s = 0.f, ss = 0.f;
    #pragma unroll
    for (int i = 0; i < 5; i++) {
        v[i] = p[i * 32 + lane];
        s  += v[i].x + v[i].y + v[i].z + v[i].w;
        ss += v[i].x * v[i].x + v[i].y * v[i].y + v[i].z * v[i].z + v[i].w * v[i].w;
    }
    #pragma unroll
    for (int o = 16; o > 0; o >>= 1) {
        s  += __shfl_xor_sync(0xffffffffu, s,  o);
        ss += __shfl_xor_sync(0xffffffffu, ss, o);
    }
    const float mean = s * (1.f / DD);
    const float var  = ss * (1.f / DD) - mean * mean;
    const float inv  = rsqrtf(var + EPS_);

    float4* o4 = (float4*)(out + row * DD);
    const float4* w4 = (const float4*)w;
    const float4* b4 = (const float4*)b;
    #pragma unroll
    for (int i = 0; i < 5; i++) {
        const int c = i * 32 + lane;
        float4 wv = w4[c], bv = b4[c], r;
        r.x = (v[i].x - mean) * inv * wv.x + bv.x;
        r.y = (v[i].y - mean) * inv * wv.y + bv.y;
        r.z = (v[i].z - mean) * inv * wv.z + bv.z;
        r.w = (v[i].w - mean) * inv * wv.w + bv.w;
        o4[c] = r;
    }
}

// ---------------- cross-attention (smem K/V) --------------------------------
#define XSMEM_BYTES 54720

__global__ __launch_bounds__(256)
void xattn_k(const float* __restrict__ Q, const float* __restrict__ K,
             const float* __restrict__ V, float* __restrict__ O)
{
    extern __shared__ float xs[];
    float* Ks = xs;
    float* Vs = xs + 6240;
    float* sc = xs + 12400;
    float* qb = xs + 13040;

    const int tid  = threadIdx.x;
    const int wid  = tid >> 5;
    const int lane = tid & 31;
    const int bh   = blockIdx.y;
    const int b    = bh / HH, h = bh % HH;
    const int q0   = blockIdx.x * 128;

    const float* Kp = K + (long)b * CN_ * DD + h * DH;
    const float* Vp = V + (long)b * CN_ * DD + h * DH;
    for (int idx = tid; idx < CN_ * DH; idx += 256) {
        const int j = idx / DH, d = idx % DH;
        Ks[j * 81 + d] = Kp[(long)j * DD + d];
        Vs[j * 80 + d] = Vp[(long)j * DD + d];
    }
    __syncthreads();

    float* scw = sc + wid * 80;
    float* qbw = qb + wid * 80;

    for (int qq = wid; qq < 128; qq += 8) {
        const int qrow = q0 + qq;
        const float* qp = Q + ((long)(b * NN_ + qrow) * DD + h * DH);
        for (int d = lane; d < DH; d += 32) qbw[d] = qp[d];
        __syncwarp();

        float mx = -1e30f;
        for (int j = lane; j < CN_; j += 32) {
            float s = 0.f;
            #pragma unroll 8
            for (int d = 0; d < DH; d++) s += qbw[d] * Ks[j * 81 + d];
            s *= SCALE_ATTN;
            scw[j] = s;
            mx = fmaxf(mx, s);
        }
        #pragma unroll
        for (int o = 16; o > 0; o >>= 1)
            mx = fmaxf(mx, __shfl_xor_sync(0xffffffffu, mx, o));

        float sum = 0.f;
        __syncwarp();
        for (int j = lane; j < CN_; j += 32) {
            float e = __expf(scw[j] - mx);
            scw[j] = e;
            sum += e;
        }
        #pragma unroll
        for (int o = 16; o > 0; o >>= 1)
            sum += __shfl_xor_sync(0xffffffffu, sum, o);
        const float inv = 1.f / sum;
        __syncwarp();

        float* op = O + ((long)(b * NN_ + qrow) * DD + h * DH);
        for (int d = lane; d < DH; d += 32) {
            float acc = 0.f;
            #pragma unroll 7
            for (int j = 0; j < CN_; j++) acc += scw[j] * Vs[j * 80 + d];
            op[d] = acc * inv;
        }
        __syncwarp();
    }
}

// ---------------- GEGLU -----------------------------------------------------
__device__ __forceinline__ float gelu1(float g) {
    return 0.5f * g * (1.f + erff(g * 0.70710678118654752f));
}

__global__ __launch_bounds__(256)
void geglu_k(const float4* __restrict__ proj, float4* __restrict__ out)
{
    const long idx = (long)blockIdx.x * 256 + threadIdx.x;
    const long row = idx / (FF_ / 4);
    const long c   = idx % (FF_ / 4);
    const float4 a = proj[row * (2 * FF_ / 4) + c];
    const float4 g = proj[row * (2 * FF_ / 4) + FF_ / 4 + c];
    float4 r;
    r.x = a.x * gelu1(g.x);
    r.y = a.y * gelu1(g.y);
    r.z = a.z * gelu1(g.z);
    r.w = a.w * gelu1(g.w);
    out[idx] = r;
}

// ---------------- host ------------------------------------------------------
static inline void gemm_nn(const float* A, const float* B, float* C,
                           int M, int N, int K, int lda, int ldb, int ldc,
                           const float* bias, const float* resid)
{
    if (N % 256 == 0) {
        dim3 grid(N / 256, (M + 127) / 128);
        gemm_mma_k<64, false><<<grid, 256, GSM64>>>(A, B, C, M, N, K, lda, ldb, ldc, bias, resid);
    } else {
        dim3 grid(N / 128, (M + 127) / 128);
        gemm_mma_k<32, false><<<grid, 256, GSM32>>>(A, B, C, M, N, K, lda, ldb, ldc, bias, resid);
    }
}

static inline void gemm_nn_b16(const float* A, const float* B, __nv_bfloat16* C,
                               int M, int N, int K)
{
    dim3 grid(N / 128, (M + 127) / 128);
    gemm_mma_k<32, true><<<grid, 256, GSM32>>>(A, B, C, M, N, K, K, N, N, nullptr, nullptr);
}

extern "C" void kernel_launch(void* const* d_in, const int* in_sizes, int n_in,
                              void* d_out, int out_size)
{
    const float* x    = (const float*)d_in[0];
    const float* ctx  = (const float*)d_in[1];
    const float* ln1w = (const float*)d_in[2];
    const float* ln1b = (const float*)d_in[3];
    const float* ln2w = (const float*)d_in[4];
    const float* ln2b = (const float*)d_in[5];
    const float* ln3w = (const float*)d_in[6];
    const float* ln3b = (const float*)d_in[7];
    const float* wq1  = (const float*)d_in[8];
    const float* wk1  = (const float*)d_in[9];
    const float* wv1  = (const float*)d_in[10];
    const float* wo1  = (const float*)d_in[11];
    const float* bo1  = (const float*)d_in[12];
    const float* wq2  = (const float*)d_in[13];
    const float* wk2  = (const float*)d_in[14];
    const float* wv2  = (const float*)d_in[15];
    const float* wo2  = (const float*)d_in[16];
    const float* bo2  = (const float*)d_in[17];
    const float* wff1 = (const float*)d_in[18];
    const float* bff1 = (const float*)d_in[19];
    const float* wff2 = (const float*)d_in[20];
    const float* bff2 = (const float*)d_in[21];
    float* out = (float*)d_out;

    float *xp, *hp, *qp, *kp, *vp, *ap, *pp, *fp;
    __nv_bfloat16 *qb, *kb, *vb;
    cudaGetSymbolAddress((void**)&xp, g_x);
    cudaGetSymbolAddress((void**)&hp, g_h);
    cudaGetSymbolAddress((void**)&qp, g_q);
    cudaGetSymbolAddress((void**)&kp, g_k);
    cudaGetSymbolAddress((void**)&vp, g_v);
    cudaGetSymbolAddress((void**)&ap, g_attn);
    cudaGetSymbolAddress((void**)&pp, g_proj);
    cudaGetSymbolAddress((void**)&fp, g_ffh);
    cudaGetSymbolAddress((void**)&qb, g_qb);
    cudaGetSymbolAddress((void**)&kb, g_kb);
    cudaGetSymbolAddress((void**)&vb, g_vb);

    cudaFuncSetAttribute(gemm_mma_k<64, false>, cudaFuncAttributeMaxDynamicSharedMemorySize, GSM64);
    cudaFuncSetAttribute(gemm_mma_k<32, false>, cudaFuncAttributeMaxDynamicSharedMemorySize, GSM32);
    cudaFuncSetAttribute(gemm_mma_k<32, true>,  cudaFuncAttributeMaxDynamicSharedMemorySize, GSM32);
    cudaFuncSetAttribute(flash_bf_k, cudaFuncAttributeMaxDynamicSharedMemorySize, FSM);
    cudaFuncSetAttribute(xattn_k,    cudaFuncAttributeMaxDynamicSharedMemorySize, XSMEM_BYTES);

    const int M = BB * NN_;
    cudaMemcpyAsync(xp, x, (long)M * DD * sizeof(float), cudaMemcpyDeviceToDevice);

    // ===== self-attention =====
    ln_k<<<M / 8, 256>>>(xp, ln1w, ln1b, hp);
    gemm_nn_b16(hp, wq1, qb, M, DD, DD);
    gemm_nn_b16(hp, wk1, kb, M, DD, DD);
    gemm_nn_b16(hp, wv1, vb, M, DD, DD);
    {
        dim3 grid(NN_ / 128, BB * HH);
        flash_bf_k<<<grid, 256, FSM>>>(qb, kb, vb, ap);
    }
    gemm_nn(ap, wo1, xp, M, DD, DD, DD, DD, DD, bo1, xp);

    // ===== cross-attention =====
    ln_k<<<M / 8, 256>>>(xp, ln2w, ln2b, hp);
    gemm_nn(hp, wq2, qp, M, DD, DD, DD, DD, DD, nullptr, nullptr);
    gemm_nn(ctx, wk2, kp, BB * CN_, DD, CDIM, CDIM, DD, DD, nullptr, nullptr);
    gemm_nn(ctx, wv2, vp, BB * CN_, DD, CDIM, CDIM, DD, DD, nullptr, nullptr);
    {
        dim3 grid(NN_ / 128, BB * HH);
        xattn_k<<<grid, 256, XSMEM_BYTES>>>(qp, kp, vp, ap);
    }
    gemm_nn(ap, wo2, xp, M, DD, DD, DD, DD, DD, bo2, xp);

    // ===== GEGLU FF =====
    ln_k<<<M / 8, 256>>>(xp, ln3w, ln3b, hp);
    gemm_nn(hp, wff1, pp, M, 2 * FF_, DD, DD, 2 * FF_, 2 * FF_, bff1, nullptr);
    geglu_k<<<(int)(((long)M * (FF_ / 4)) / 256), 256>>>((const float4*)pp, (float4*)fp);
    gemm_nn(fp, wff2, out, M, DD, FF_, FF_, DD, DD, bff2, xp);
}

// round 13
// speedup vs baseline: 1.0022x; 1.0022x over previous
#include <cuda_runtime.h>
#include <cuda_bf16.h>
#include <math.h>
#include <stdint.h>

#define BB   2
#define NN_  4096
#define DD   640
#define HH   8
#define DH   80
#define CN_  77
#define CDIM 768
#define FF_  2560
#define EPS_ 1e-5f
#define SCALE_ATTN 0.11180339887498948f

// ---------------- device scratch (static; no cudaMalloc) -------------------
__device__ float g_x   [(size_t)BB * NN_ * DD];
__device__ float g_h   [(size_t)BB * NN_ * DD];
__device__ float g_q   [(size_t)BB * NN_ * DD];
__device__ float g_k   [(size_t)BB * NN_ * DD];
__device__ float g_v   [(size_t)BB * NN_ * DD];
__device__ float g_attn[(size_t)BB * NN_ * DD];
__device__ float g_proj[(size_t)BB * NN_ * 2 * FF_];
__device__ float g_ffh [(size_t)BB * NN_ * FF_];
__device__ __nv_bfloat16 g_qb[(size_t)BB * NN_ * DD];
__device__ __nv_bfloat16 g_kb[(size_t)BB * NN_ * DD];
__device__ __nv_bfloat16 g_vb[(size_t)BB * NN_ * DD];

// ---------------- helpers ---------------------------------------------------
__device__ __forceinline__ void mma_tf32(float* c, const uint32_t* a, const uint32_t* b) {
    asm volatile(
        "mma.sync.aligned.m16n8k8.row.col.f32.tf32.tf32.f32 "
        "{%0,%1,%2,%3}, {%4,%5,%6,%7}, {%8,%9}, {%0,%1,%2,%3};\n"
        : "+f"(c[0]), "+f"(c[1]), "+f"(c[2]), "+f"(c[3])
        : "r"(a[0]), "r"(a[1]), "r"(a[2]), "r"(a[3]), "r"(b[0]), "r"(b[1]));
}
__device__ __forceinline__ void mma_bf16(float* c, const uint32_t* a, const uint32_t* b) {
    asm volatile(
        "mma.sync.aligned.m16n8k16.row.col.f32.bf16.bf16.f32 "
        "{%0,%1,%2,%3}, {%4,%5,%6,%7}, {%8,%9}, {%0,%1,%2,%3};\n"
        : "+f"(c[0]), "+f"(c[1]), "+f"(c[2]), "+f"(c[3])
        : "r"(a[0]), "r"(a[1]), "r"(a[2]), "r"(a[3]), "r"(b[0]), "r"(b[1]));
}
__device__ __forceinline__ uint32_t packbf(float lo, float hi) {
    uint32_t d;
    asm("cvt.rn.bf16x2.f32 %0, %1, %2;" : "=r"(d) : "f"(hi), "f"(lo));
    return d;
}
__device__ __forceinline__ void cp16(uint32_t s, const void* g) {
    asm volatile("cp.async.ca.shared.global [%0], [%1], 16;\n" :: "r"(s), "l"(g));
}
__device__ __forceinline__ void cp16z(uint32_t s, const void* g, bool valid) {
    int sz = valid ? 16 : 0;
    asm volatile("cp.async.ca.shared.global [%0], [%1], 16, %2;\n"
                 :: "r"(s), "l"(g), "r"(sz));
}
__device__ __forceinline__ void ldsm_x4(uint32_t& r0, uint32_t& r1, uint32_t& r2,
                                        uint32_t& r3, uint32_t sa) {
    asm volatile("ldmatrix.sync.aligned.m8n8.x4.shared.b16 {%0,%1,%2,%3}, [%4];"
                 : "=r"(r0), "=r"(r1), "=r"(r2), "=r"(r3) : "r"(sa));
}
__device__ __forceinline__ void ldsm_x4_t(uint32_t& r0, uint32_t& r1, uint32_t& r2,
                                          uint32_t& r3, uint32_t sa) {
    asm volatile("ldmatrix.sync.aligned.m8n8.x4.trans.shared.b16 {%0,%1,%2,%3}, [%4];"
                 : "=r"(r0), "=r"(r1), "=r"(r2), "=r"(r3) : "r"(sa));
}

// ---------------------------------------------------------------------------
// TF32 mma.sync GEMM; 4-stage cp.async pipeline, one barrier per K-tile.
// ---------------------------------------------------------------------------
#define AST 20
#define ABUFW (128 * AST)           // words per A stage

template<int WN, bool OB>
__global__ __launch_bounds__(256, (WN == 32) ? 2 : 1)
void gemm_mma_k(const float* __restrict__ A, const float* __restrict__ B,
                void* __restrict__ Cv,
                int M, int N, int K, int lda, int ldb, int ldc,
                const float* __restrict__ bias,
                const float* __restrict__ resid)
{
    constexpr int BN  = 4 * WN;
    constexpr int BST = BN + 4;
    constexpr int NF  = WN / 8;
    constexpr int BBUFW = 16 * BST;  // words per B stage
    extern __shared__ uint32_t dsm[];
    uint32_t* const Bsb = dsm + 4 * ABUFW;

    const int tid  = threadIdx.x;
    const int wid  = tid >> 5;
    const int lane = tid & 31;
    const int g    = lane >> 2;
    const int tg   = lane & 3;
    const int wm   = wid & 1;
    const int wn   = wid >> 1;
    const int m0   = blockIdx.y * 128;
    const int n0   = blockIdx.x * BN;

    const int arow = lane & 15;
    const int acol = (lane >> 4) * 4;

    const int am = tid >> 2;
    const int ac = (tid & 3) * 4;
    const bool av0 = (m0 + am      < M);
    const bool av1 = (m0 + am + 64 < M);
    const long aoff0 = (long)(av0 ? m0 + am      : 0) * lda;
    const long aoff1 = (long)(av1 ? m0 + am + 64 : 0) * lda;

    const uint32_t asb = (uint32_t)__cvta_generic_to_shared(dsm);
    const uint32_t bsb = (uint32_t)__cvta_generic_to_shared(Bsb);
    constexpr int BCH = (16 * BN / 4) / 256;

    #define GM_ISSUE(k0, slot)                                                        \
    {                                                                                  \
        cp16z(asb + (uint32_t)((slot) * ABUFW + am * AST + ac) * 4u,                   \
              A + aoff0 + (k0) + ac, av0);                                             \
        cp16z(asb + (uint32_t)((slot) * ABUFW + (am + 64) * AST + ac) * 4u,            \
              A + aoff1 + (k0) + ac, av1);                                             \
        _Pragma("unroll")                                                              \
        for (int i = 0; i < BCH; i++) {                                                \
            const int idx = i * 256 + tid;                                             \
            const int row = idx / (BN / 4);                                            \
            const int col = (idx % (BN / 4)) * 4;                                      \
            cp16(bsb + (uint32_t)((slot) * BBUFW + row * BST + col) * 4u,              \
                 B + (long)((k0) + row) * ldb + n0 + col);                             \
        }                                                                              \
        asm volatile("cp.async.commit_group;\n" ::);                                   \
    }

    float acc[4][NF][4];
    #pragma unroll
    for (int i = 0; i < 4; i++)
        #pragma unroll
        for (int j = 0; j < NF; j++)
            #pragma unroll
            for (int q = 0; q < 4; q++) acc[i][j][q] = 0.f;

    const int NT = K / 16;
    GM_ISSUE(0, 0);
    GM_ISSUE(16, 1);
    GM_ISSUE(32, 2);

    for (int kt = 0; kt < NT; kt++) {
        const int slot = kt & 3;
        if (kt + 3 < NT) {
            asm volatile("cp.async.wait_group 2;\n" ::);
            __syncthreads();
            GM_ISSUE((kt + 3) * 16, (kt + 3) & 3);
        } else {
            asm volatile("cp.async.wait_group 0;\n" ::);
            __syncthreads();
        }

        const uint32_t abase = asb + (uint32_t)(slot * ABUFW) * 4u;
        const uint32_t* Bb = Bsb + slot * BBUFW;

        #pragma unroll
        for (int kk = 0; kk < 16; kk += 8) {
            uint32_t af[4][4], bf[NF][2];
            #pragma unroll
            for (int mf = 0; mf < 4; mf++) {
                const uint32_t sa = abase +
                    (uint32_t)(((wm * 64 + mf * 16 + arow) * AST + kk + acol) * 4);
                ldsm_x4(af[mf][0], af[mf][1], af[mf][2], af[mf][3], sa);
            }
            #pragma unroll
            for (int nf = 0; nf < NF; nf++) {
                const int cb = wn * WN + nf * 8 + g;
                bf[nf][0] = Bb[(kk + tg)     * BST + cb];
                bf[nf][1] = Bb[(kk + tg + 4) * BST + cb];
            }
            #pragma unroll
            for (int mf = 0; mf < 4; mf++)
                #pragma unroll
                for (int nf = 0; nf < NF; nf++)
                    mma_tf32(acc[mf][nf], af[mf], bf[nf]);
        }
    }

    #pragma unroll
    for (int mf = 0; mf < 4; mf++) {
        const int r0 = m0 + wm * 64 + mf * 16 + g;
        const int r1 = r0 + 8;
        #pragma unroll
        for (int nf = 0; nf < NF; nf++) {
            const int cc = n0 + wn * WN + nf * 8 + tg * 2;
            float b0 = 0.f, b1 = 0.f;
            if (bias) { b0 = bias[cc]; b1 = bias[cc + 1]; }
            if (r0 < M) {
                float v0 = acc[mf][nf][0] + b0;
                float v1 = acc[mf][nf][1] + b1;
                if (resid) {
                    v0 += resid[(long)r0 * ldc + cc];
                    v1 += resid[(long)r0 * ldc + cc + 1];
                }
                if (OB) *(uint32_t*)((__nv_bfloat16*)Cv + (long)r0 * ldc + cc) = packbf(v0, v1);
                else    *(float2*)((float*)Cv + (long)r0 * ldc + cc) = make_float2(v0, v1);
            }
            if (r1 < M) {
                float v0 = acc[mf][nf][2] + b0;
                float v1 = acc[mf][nf][3] + b1;
                if (resid) {
                    v0 += resid[(long)r1 * ldc + cc];
                    v1 += resid[(long)r1 * ldc + cc + 1];
                }
                if (OB) *(uint32_t*)((__nv_bfloat16*)Cv + (long)r1 * ldc + cc) = packbf(v0, v1);
                else    *(float2*)((float*)Cv + (long)r1 * ldc + cc) = make_float2(v0, v1);
            }
        }
    }
}

#define GSM64 ((4 * ABUFW + 4 * 16 * (256 + 4)) * 4)   // 107520
#define GSM32 ((4 * ABUFW + 4 * 16 * (128 + 4)) * 4)   // 74752

// ---------------------------------------------------------------------------
// bf16 flash attention; 3-stage cp.async pipeline, one barrier per key tile.
// ---------------------------------------------------------------------------
#define FKST 88
#define FSTG 22528                 // K(11264) + V(11264) per stage
#define FSM3 (3 * FSTG)            // 67584

__global__ void __launch_bounds__(256, 2)
flash_bf_k(const __nv_bfloat16* __restrict__ Q, const __nv_bfloat16* __restrict__ K,
           const __nv_bfloat16* __restrict__ V, float* __restrict__ O)
{
    extern __shared__ char fsmc[];
    const uint32_t sb = (uint32_t)__cvta_generic_to_shared(fsmc);

    const int tid  = threadIdx.x;
    const int wid  = tid >> 5;
    const int lane = tid & 31;
    const int g    = lane >> 2;
    const int tg   = lane & 3;
    const int bh   = blockIdx.y;
    const int b    = bh / HH, h = bh % HH;
    const int row0 = blockIdx.x * 128;
    const int NT   = NN_ / 64;

    const __nv_bfloat16* Qp = Q + (long)(b * NN_ + row0) * DD + h * DH;
    const __nv_bfloat16* Kp = K + (long)b * NN_ * DD + h * DH;
    const __nv_bfloat16* Vp = V + (long)b * NN_ * DD + h * DH;
    float* Op = O + (long)(b * NN_ + row0) * DD + h * DH;

    const int krow = (lane & 7) + ((lane >> 4) << 3);
    const int kseg = ((lane >> 3) & 1) * 16;
    const int vrow = lane & 15;
    const int vseg = lane >> 4;

    uint32_t qa[5][4];
    {
        const __nv_bfloat16* q0 = Qp + (long)(wid * 16 + g) * DD;
        const __nv_bfloat16* q1 = q0 + 8 * DD;
        #pragma unroll
        for (int kc = 0; kc < 5; kc++) {
            const int c = kc * 16 + 2 * tg;
            qa[kc][0] = *(const uint32_t*)(q0 + c);
            qa[kc][1] = *(const uint32_t*)(q1 + c);
            qa[kc][2] = *(const uint32_t*)(q0 + c + 8);
            qa[kc][3] = *(const uint32_t*)(q1 + c + 8);
        }
    }

    float oa[10][4];
    #pragma unroll
    for (int nf = 0; nf < 10; nf++)
        #pragma unroll
        for (int q = 0; q < 4; q++) oa[nf][q] = 0.f;
    float mr0 = -1e30f, mr1 = -1e30f, lr0 = 0.f, lr1 = 0.f;

    #define FB_ISSUE(kt, slot)                                                         \
    {                                                                                   \
        for (int i = tid; i < 640; i += 256) {                                          \
            const int r = i / 10, c = i % 10;                                           \
            cp16(sb + (uint32_t)((slot) * FSTG + r * (FKST * 2) + c * 16),              \
                 Kp + (long)((kt) * 64 + r) * DD + c * 8);                              \
        }                                                                               \
        for (int i = tid; i < 640; i += 256) {                                          \
            const int r = i / 10, c = i % 10;                                           \
            cp16(sb + (uint32_t)((slot) * FSTG + 11264 + r * (FKST * 2) + c * 16),      \
                 Vp + (long)((kt) * 64 + r) * DD + c * 8);                              \
        }                                                                               \
        asm volatile("cp.async.commit_group;\n" ::);                                    \
    }

    FB_ISSUE(0, 0);
    FB_ISSUE(1, 1);
    int s0 = 0;

    for (int kt = 0; kt < NT; kt++) {
        if (kt + 2 < NT) {
            asm volatile("cp.async.wait_group 1;\n" ::);
            __syncthreads();
            int sn = s0 + 2; if (sn >= 3) sn -= 3;
            FB_ISSUE(kt + 2, sn);
        } else {
            asm volatile("cp.async.wait_group 0;\n" ::);
            __syncthreads();
        }

        const uint32_t kbase = sb + (uint32_t)(s0 * FSTG);
        const uint32_t vbase = kbase + 11264;

        // ---- S = Q K^T ----
        float sa[8][4];
        #pragma unroll
        for (int nf = 0; nf < 8; nf++)
            #pragma unroll
            for (int q = 0; q < 4; q++) sa[nf][q] = 0.f;

        #pragma unroll
        for (int kc = 0; kc < 5; kc++) {
            #pragma unroll
            for (int nfp = 0; nfp < 4; nfp++) {
                uint32_t b0, b1, b2, b3;
                ldsm_x4(b0, b1, b2, b3,
                        kbase + (uint32_t)((nfp * 16 + krow) * (FKST * 2) + kc * 32 + kseg));
                uint32_t ba[2] = {b0, b1};
                uint32_t bb[2] = {b2, b3};
                mma_bf16(sa[2 * nfp],     qa[kc], ba);
                mma_bf16(sa[2 * nfp + 1], qa[kc], bb);
            }
        }

        // ---- online softmax; P stays in registers ----
        float rm0 = -1e30f, rm1 = -1e30f;
        #pragma unroll
        for (int nf = 0; nf < 8; nf++) {
            rm0 = fmaxf(rm0, fmaxf(sa[nf][0], sa[nf][1]));
            rm1 = fmaxf(rm1, fmaxf(sa[nf][2], sa[nf][3]));
        }
        rm0 *= SCALE_ATTN; rm1 *= SCALE_ATTN;
        rm0 = fmaxf(rm0, __shfl_xor_sync(0xffffffffu, rm0, 1));
        rm0 = fmaxf(rm0, __shfl_xor_sync(0xffffffffu, rm0, 2));
        rm1 = fmaxf(rm1, __shfl_xor_sync(0xffffffffu, rm1, 1));
        rm1 = fmaxf(rm1, __shfl_xor_sync(0xffffffffu, rm1, 2));

        const float mn0 = fmaxf(mr0, rm0);
        const float mn1 = fmaxf(mr1, rm1);
        const float cr0 = __expf(mr0 - mn0);
        const float cr1 = __expf(mr1 - mn1);

        uint32_t pa[4][4];
        float rs0 = 0.f, rs1 = 0.f;
        #pragma unroll
        for (int nf = 0; nf < 8; nf++) {
            float p00 = __expf(sa[nf][0] * SCALE_ATTN - mn0);
            float p01 = __expf(sa[nf][1] * SCALE_ATTN - mn0);
            float p10 = __expf(sa[nf][2] * SCALE_ATTN - mn1);
            float p11 = __expf(sa[nf][3] * SCALE_ATTN - mn1);
            rs0 += p00 + p01;
            rs1 += p10 + p11;
            const int kc = nf >> 1, hi = (nf & 1) ? 2 : 0;
            pa[kc][hi]     = packbf(p00, p01);
            pa[kc][hi + 1] = packbf(p10, p11);
        }
        rs0 += __shfl_xor_sync(0xffffffffu, rs0, 1);
        rs0 += __shfl_xor_sync(0xffffffffu, rs0, 2);
        rs1 += __shfl_xor_sync(0xffffffffu, rs1, 1);
        rs1 += __shfl_xor_sync(0xffffffffu, rs1, 2);

        lr0 = lr0 * cr0 + rs0;  mr0 = mn0;
        lr1 = lr1 * cr1 + rs1;  mr1 = mn1;

        #pragma unroll
        for (int nf = 0; nf < 10; nf++) {
            oa[nf][0] *= cr0; oa[nf][1] *= cr0;
            oa[nf][2] *= cr1; oa[nf][3] *= cr1;
        }

        // ---- O += P V ----
        #pragma unroll
        for (int kc = 0; kc < 4; kc++) {
            #pragma unroll
            for (int nfp = 0; nfp < 5; nfp++) {
                uint32_t b0, b1, b2, b3;
                ldsm_x4_t(b0, b1, b2, b3,
                          vbase + (uint32_t)((kc * 16 + vrow) * (FKST * 2)
                                             + (nfp * 2 + vseg) * 16));
                uint32_t ba[2] = {b0, b1};
                uint32_t bb[2] = {b2, b3};
                mma_bf16(oa[2 * nfp],     pa[kc], ba);
                mma_bf16(oa[2 * nfp + 1], pa[kc], bb);
            }
        }

        s0 = (s0 == 2) ? 0 : s0 + 1;
    }

    const float inv0 = 1.f / lr0;
    const float inv1 = 1.f / lr1;
    #pragma unroll
    for (int nf = 0; nf < 10; nf++) {
        const int cc = nf * 8 + tg * 2;
        *(float2*)(Op + (long)(wid * 16 + g)     * DD + cc) =
            make_float2(oa[nf][0] * inv0, oa[nf][1] * inv0);
        *(float2*)(Op + (long)(wid * 16 + g + 8) * DD + cc) =
            make_float2(oa[nf][2] * inv1, oa[nf][3] * inv1);
    }
}

// ---------------- LayerNorm (warp per row) ----------------------------------
__global__ __launch_bounds__(256)
void ln_k(const float* __restrict__ x, const float* __restrict__ w,
          const float* __restrict__ b, float* __restrict__ out)
{
    const int lane = threadIdx.x & 31;
    const long row = (long)blockIdx.x * 8 + (threadIdx.x >> 5);
    const float4* p = (const float4*)(x + row * DD);

    float4 v[5];
    float s = 0.f, ss = 0.f;
    #pragma unroll
    for (int i = 0; i < 5; i++) {
        v[i] = p[i * 32 + lane];
        s  += v[i].x + v[i].y + v[i].z + v[i].w;
        ss += v[i].x * v[i].x + v[i].y * v[i].y + v[i].z * v[i].z + v[i].w * v[i].w;
    }
    #pragma unroll
    for (int o = 16; o > 0; o >>= 1) {
        s  += __shfl_xor_sync(0xffffffffu, s,  o);
        ss += __shfl_xor_sync(0xffffffffu, ss, o);
    }
    const float mean = s * (1.f / DD);
    const float var  = ss * (1.f / DD) - mean * mean;
    const float inv  = rsqrtf(var + EPS_);

    float4* o4 = (float4*)(out + row * DD);
    const float4* w4 = (const float4*)w;
    const float4* b4 = (const float4*)b;
    #pragma unroll
    for (int i = 0; i < 5; i++) {
        const int c = i * 32 + lane;
        float4 wv = w4[c], bv = b4[c], r;
        r.x = (v[i].x - mean) * inv * wv.x + bv.x;
        r.y = (v[i].y - mean) * inv * wv.y + bv.y;
        r.z = (v[i].z - mean) * inv * wv.z + bv.z;
        r.w = (v[i].w - mean) * inv * wv.w + bv.w;
        o4[c] = r;
    }
}

// ---------------- cross-attention (smem K/V) --------------------------------
#define XSMEM_BYTES 54720

__global__ __launch_bounds__(256)
void xattn_k(const float* __restrict__ Q, const float* __restrict__ K,
             const float* __restrict__ V, float* __restrict__ O)
{
    extern __shared__ float xs[];
    float* Ks = xs;
    float* Vs = xs + 6240;
    float* sc = xs + 12400;
    float* qb = xs + 13040;

    const int tid  = threadIdx.x;
    const int wid  = tid >> 5;
    const int lane = tid & 31;
    const int bh   = blockIdx.y;
    const int b    = bh / HH, h = bh % HH;
    const int q0   = blockIdx.x * 128;

    const float* Kp = K + (long)b * CN_ * DD + h * DH;
    const float* Vp = V + (long)b * CN_ * DD + h * DH;
    for (int idx = tid; idx < CN_ * DH; idx += 256) {
        const int j = idx / DH, d = idx % DH;
        Ks[j * 81 + d] = Kp[(long)j * DD + d];
        Vs[j * 80 + d] = Vp[(long)j * DD + d];
    }
    __syncthreads();

    float* scw = sc + wid * 80;
    float* qbw = qb + wid * 80;

    for (int qq = wid; qq < 128; qq += 8) {
        const int qrow = q0 + qq;
        const float* qp = Q + ((long)(b * NN_ + qrow) * DD + h * DH);
        for (int d = lane; d < DH; d += 32) qbw[d] = qp[d];
        __syncwarp();

        float mx = -1e30f;
        for (int j = lane; j < CN_; j += 32) {
            float s = 0.f;
            #pragma unroll 8
            for (int d = 0; d < DH; d++) s += qbw[d] * Ks[j * 81 + d];
            s *= SCALE_ATTN;
            scw[j] = s;
            mx = fmaxf(mx, s);
        }
        #pragma unroll
        for (int o = 16; o > 0; o >>= 1)
            mx = fmaxf(mx, __shfl_xor_sync(0xffffffffu, mx, o));

        float sum = 0.f;
        __syncwarp();
        for (int j = lane; j < CN_; j += 32) {
            float e = __expf(scw[j] - mx);
            scw[j] = e;
            sum += e;
        }
        #pragma unroll
        for (int o = 16; o > 0; o >>= 1)
            sum += __shfl_xor_sync(0xffffffffu, sum, o);
        const float inv = 1.f / sum;
        __syncwarp();

        float* op = O + ((long)(b * NN_ + qrow) * DD + h * DH);
        for (int d = lane; d < DH; d += 32) {
            float acc = 0.f;
            #pragma unroll 7
            for (int j = 0; j < CN_; j++) acc += scw[j] * Vs[j * 80 + d];
            op[d] = acc * inv;
        }
        __syncwarp();
    }
}

// ---------------- GEGLU -----------------------------------------------------
__device__ __forceinline__ float gelu1(float g) {
    return 0.5f * g * (1.f + erff(g * 0.70710678118654752f));
}

__global__ __launch_bounds__(256)
void geglu_k(const float4* __restrict__ proj, float4* __restrict__ out)
{
    const long idx = (long)blockIdx.x * 256 + threadIdx.x;
    const long row = idx / (FF_ / 4);
    const long c   = idx % (FF_ / 4);
    const float4 a = proj[row * (2 * FF_ / 4) + c];
    const float4 g = proj[row * (2 * FF_ / 4) + FF_ / 4 + c];
    float4 r;
    r.x = a.x * gelu1(g.x);
    r.y = a.y * gelu1(g.y);
    r.z = a.z * gelu1(g.z);
    r.w = a.w * gelu1(g.w);
    out[idx] = r;
}

// ---------------- host ------------------------------------------------------
static inline void gemm_nn(const float* A, const float* B, float* C,
                           int M, int N, int K, int lda, int ldb, int ldc,
                           const float* bias, const float* resid)
{
    if (N % 256 == 0) {
        dim3 grid(N / 256, (M + 127) / 128);
        gemm_mma_k<64, false><<<grid, 256, GSM64>>>(A, B, C, M, N, K, lda, ldb, ldc, bias, resid);
    } else {
        dim3 grid(N / 128, (M + 127) / 128);
        gemm_mma_k<32, false><<<grid, 256, GSM32>>>(A, B, C, M, N, K, lda, ldb, ldc, bias, resid);
    }
}

static inline void gemm_nn_b16(const float* A, const float* B, __nv_bfloat16* C,
                               int M, int N, int K)
{
    dim3 grid(N / 128, (M + 127) / 128);
    gemm_mma_k<32, true><<<grid, 256, GSM32>>>(A, B, C, M, N, K, K, N, N, nullptr, nullptr);
}

extern "C" void kernel_launch(void* const* d_in, const int* in_sizes, int n_in,
                              void* d_out, int out_size)
{
    const float* x    = (const float*)d_in[0];
    const float* ctx  = (const float*)d_in[1];
    const float* ln1w = (const float*)d_in[2];
    const float* ln1b = (const float*)d_in[3];
    const float* ln2w = (const float*)d_in[4];
    const float* ln2b = (const float*)d_in[5];
    const float* ln3w = (const float*)d_in[6];
    const float* ln3b = (const float*)d_in[7];
    const float* wq1  = (const float*)d_in[8];
    const float* wk1  = (const float*)d_in[9];
    const float* wv1  = (const float*)d_in[10];
    const float* wo1  = (const float*)d_in[11];
    const float* bo1  = (const float*)d_in[12];
    const float* wq2  = (const float*)d_in[13];
    const float* wk2  = (const float*)d_in[14];
    const float* wv2  = (const float*)d_in[15];
    const float* wo2  = (const float*)d_in[16];
    const float* bo2  = (const float*)d_in[17];
    const float* wff1 = (const float*)d_in[18];
    const float* bff1 = (const float*)d_in[19];
    const float* wff2 = (const float*)d_in[20];
    const float* bff2 = (const float*)d_in[21];
    float* out = (float*)d_out;

    float *xp, *hp, *qp, *kp, *vp, *ap, *pp, *fp;
    __nv_bfloat16 *qb, *kb, *vb;
    cudaGetSymbolAddress((void**)&xp, g_x);
    cudaGetSymbolAddress((void**)&hp, g_h);
    cudaGetSymbolAddress((void**)&qp, g_q);
    cudaGetSymbolAddress((void**)&kp, g_k);
    cudaGetSymbolAddress((void**)&vp, g_v);
    cudaGetSymbolAddress((void**)&ap, g_attn);
    cudaGetSymbolAddress((void**)&pp, g_proj);
    cudaGetSymbolAddress((void**)&fp, g_ffh);
    cudaGetSymbolAddress((void**)&qb, g_qb);
    cudaGetSymbolAddress((void**)&kb, g_kb);
    cudaGetSymbolAddress((void**)&vb, g_vb);

    cudaFuncSetAttribute(gemm_mma_k<64, false>, cudaFuncAttributeMaxDynamicSharedMemorySize, GSM64);
    cudaFuncSetAttribute(gemm_mma_k<32, false>, cudaFuncAttributeMaxDynamicSharedMemorySize, GSM32);
    cudaFuncSetAttribute(gemm_mma_k<32, true>,  cudaFuncAttributeMaxDynamicSharedMemorySize, GSM32);
    cudaFuncSetAttribute(flash_bf_k, cudaFuncAttributeMaxDynamicSharedMemorySize, FSM3);
    cudaFuncSetAttribute(xattn_k,    cudaFuncAttributeMaxDynamicSharedMemorySize, XSMEM_BYTES);

    const int M = BB * NN_;
    cudaMemcpyAsync(xp, x, (long)M * DD * sizeof(float), cudaMemcpyDeviceToDevice);

    // ===== self-attention =====
    ln_k<<<M / 8, 256>>>(xp, ln1w, ln1b, hp);
    gemm_nn_b16(hp, wq1, qb, M, DD, DD);
    gemm_nn_b16(hp, wk1, kb, M, DD, DD);
    gemm_nn_b16(hp, wv1, vb, M, DD, DD);
    {
        dim3 grid(NN_ / 128, BB * HH);
        flash_bf_k<<<grid, 256, FSM3>>>(qb, kb, vb, ap);
    }
    gemm_nn(ap, wo1, xp, M, DD, DD, DD, DD, DD, bo1, xp);

    // ===== cross-attention =====
    ln_k<<<M / 8, 256>>>(xp, ln2w, ln2b, hp);
    gemm_nn(hp, wq2, qp, M, DD, DD, DD, DD, DD, nullptr, nullptr);
    gemm_nn(ctx, wk2, kp, BB * CN_, DD, CDIM, CDIM, DD, DD, nullptr, nullptr);
    gemm_nn(ctx, wv2, vp, BB * CN_, DD, CDIM, CDIM, DD, DD, nullptr, nullptr);
    {
        dim3 grid(NN_ / 128, BB * HH);
        xattn_k<<<grid, 256, XSMEM_BYTES>>>(qp, kp, vp, ap);
    }
    gemm_nn(ap, wo2, xp, M, DD, DD, DD, DD, DD, bo2, xp);

    // ===== GEGLU FF =====
    ln_k<<<M / 8, 256>>>(xp, ln3w, ln3b, hp);
    gemm_nn(hp, wff1, pp, M, 2 * FF_, DD, DD, 2 * FF_, 2 * FF_, bff1, nullptr);
    geglu_k<<<(int)(((long)M * (FF_ / 4)) / 256), 256>>>((const float4*)pp, (float4*)fp);
    gemm_nn(fp, wff2, out, M, DD, FF_, FF_, DD, DD, bff2, xp);
}

// round 15
// speedup vs baseline: 1.0705x; 1.0681x over previous
#include <cuda_runtime.h>
#include <cuda_bf16.h>
#include <math.h>
#include <stdint.h>

#define BB   2
#define NN_  4096
#define DD   640
#define HH   8
#define DH   80
#define CN_  77
#define CDIM 768
#define FF_  2560
#define EPS_ 1e-5f
#define SCALE_ATTN 0.11180339887498948f

// ---------------- device scratch ------------------------------------------
__device__ float g_x   [(size_t)BB * NN_ * DD];
__device__ float g_h   [(size_t)BB * NN_ * DD];
__device__ float g_q   [(size_t)BB * NN_ * DD];
__device__ float g_k   [(size_t)BB * NN_ * DD];
__device__ float g_v   [(size_t)BB * NN_ * DD];
__device__ float g_attn[(size_t)BB * NN_ * DD];
__device__ float g_proj[(size_t)BB * NN_ * 2 * FF_];
__device__ float g_ffh [(size_t)BB * NN_ * FF_];
__device__ __nv_bfloat16 g_qb[(size_t)BB * NN_ * DD];
__device__ __nv_bfloat16 g_kb[(size_t)BB * NN_ * DD];
__device__ __nv_bfloat16 g_vb[(size_t)BB * NN_ * DD];

// ---------------- helpers --------------------------------------------------
__device__ __forceinline__ void mma_tf32(float* c, const uint32_t* a, const uint32_t* b) {
    asm volatile(
        "mma.sync.aligned.m16n8k8.row.col.f32.tf32.tf32.f32 "
        "{%0,%1,%2,%3}, {%4,%5,%6,%7}, {%8,%9}, {%0,%1,%2,%3};\n"
        : "+f"(c[0]), "+f"(c[1]), "+f"(c[2]), "+f"(c[3])
        : "r"(a[0]), "r"(a[1]), "r"(a[2]), "r"(a[3]), "r"(b[0]), "r"(b[1]));
}
__device__ __forceinline__ void mma_bf16(float* c, const uint32_t* a, const uint32_t* b) {
    asm volatile(
        "mma.sync.aligned.m16n8k16.row.col.f32.bf16.bf16.f32 "
        "{%0,%1,%2,%3}, {%4,%5,%6,%7}, {%8,%9}, {%0,%1,%2,%3};\n"
        : "+f"(c[0]), "+f"(c[1]), "+f"(c[2]), "+f"(c[3])
        : "r"(a[0]), "r"(a[1]), "r"(a[2]), "r"(a[3]), "r"(b[0]), "r"(b[1]));
}
__device__ __forceinline__ uint32_t packbf(float lo, float hi) {
    uint32_t d;
    asm("cvt.rn.bf16x2.f32 %0, %1, %2;" : "=r"(d) : "f"(hi), "f"(lo));
    return d;
}
__device__ __forceinline__ void cp16(uint32_t s, const void* g) {
    asm volatile("cp.async.ca.shared.global [%0], [%1], 16;\n" :: "r"(s), "l"(g));
}
__device__ __forceinline__ void cp16z(uint32_t s, const void* g, bool valid) {
    int sz = valid ? 16 : 0;
    asm volatile("cp.async.ca.shared.global [%0], [%1], 16, %2;\n"
                 :: "r"(s), "l"(g), "r"(sz));
}
__device__ __forceinline__ void ldsm_x4(uint32_t& r0, uint32_t& r1, uint32_t& r2,
                                        uint32_t& r3, uint32_t sa) {
    asm volatile("ldmatrix.sync.aligned.m8n8.x4.shared.b16 {%0,%1,%2,%3}, [%4];"
                 : "=r"(r0), "=r"(r1), "=r"(r2), "=r"(r3) : "r"(sa));
}
__device__ __forceinline__ void ldsm_x4_t(uint32_t& r0, uint32_t& r1, uint32_t& r2,
                                          uint32_t& r3, uint32_t sa) {
    asm volatile("ldmatrix.sync.aligned.m8n8.x4.trans.shared.b16 {%0,%1,%2,%3}, [%4];"
                 : "=r"(r0), "=r"(r1), "=r"(r2), "=r"(r3) : "r"(sa));
}

// ---------------------------------------------------------------------------
// TF32 GEMM, 4-stage cp.async pipeline. Templated tile:
//   MT=128: 2m x (8/2)n warps, warp 64 x WN.   MT=64: 8 n-warps, warp 64 x WN.
//   Optional z-batching: blockIdx.z selects (B,C) from {B,B2,B3},{C,C2,C3}.
// ---------------------------------------------------------------------------
#define AST 20

template<int MT, int WN, bool OB>
__global__ __launch_bounds__(256, (MT == 64) ? 3 : ((WN == 32) ? 2 : 1))
void gemm_mma_k(const float* __restrict__ A, const float* __restrict__ B,
                void* __restrict__ Cv,
                int M, int N, int K, int lda, int ldb, int ldc,
                const float* __restrict__ bias,
                const float* __restrict__ resid,
                const float* __restrict__ B2, void* __restrict__ C2,
                const float* __restrict__ B3, void* __restrict__ C3)
{
    constexpr int WM    = MT / 64;           // 2 or 1
    constexpr int NWN   = 8 / WM;            // n-warps: 4 or 8
    constexpr int BN    = NWN * WN;
    constexpr int BST   = BN + 4;
    constexpr int NF    = WN / 8;
    constexpr int ABUFW = MT * AST;
    constexpr int BBUFW = 16 * BST;
    extern __shared__ uint32_t dsm[];
    uint32_t* const Bsb = dsm + 4 * ABUFW;

    if (blockIdx.z == 1)      { B = B2; Cv = C2; }
    else if (blockIdx.z == 2) { B = B3; Cv = C3; }

    const int tid  = threadIdx.x;
    const int wid  = tid >> 5;
    const int lane = tid & 31;
    const int g    = lane >> 2;
    const int tg   = lane & 3;
    const int wm   = (WM == 2) ? (wid & 1) : 0;
    const int wn   = (WM == 2) ? (wid >> 1) : wid;
    const int m0   = blockIdx.y * MT;
    const int n0   = blockIdx.x * BN;

    const int arow = lane & 15;
    const int acol = (lane >> 4) * 4;

    const int am = tid >> 2;                 // 0..63
    const int ac = (tid & 3) * 4;
    const bool av0 = (m0 + am      < M);
    const bool av1 = (MT == 128) && (m0 + am + 64 < M);
    const long aoff0 = (long)(av0 ? m0 + am      : 0) * lda;
    const long aoff1 = (long)(av1 ? m0 + am + 64 : 0) * lda;

    const uint32_t asb = (uint32_t)__cvta_generic_to_shared(dsm);
    const uint32_t bsb = (uint32_t)__cvta_generic_to_shared(Bsb);
    constexpr int BCH = (16 * BN / 4) / 256;

    #define GM_ISSUE(k0, slot)                                                        \
    {                                                                                  \
        cp16z(asb + (uint32_t)((slot) * ABUFW + am * AST + ac) * 4u,                   \
              A + aoff0 + (k0) + ac, av0);                                             \
        if (MT == 128)                                                                 \
            cp16z(asb + (uint32_t)((slot) * ABUFW + (am + 64) * AST + ac) * 4u,        \
                  A + aoff1 + (k0) + ac, av1);                                         \
        _Pragma("unroll")                                                              \
        for (int i = 0; i < BCH; i++) {                                                \
            const int idx = i * 256 + tid;                                             \
            const int row = idx / (BN / 4);                                            \
            const int col = (idx % (BN / 4)) * 4;                                      \
            cp16(bsb + (uint32_t)((slot) * BBUFW + row * BST + col) * 4u,              \
                 B + (long)((k0) + row) * ldb + n0 + col);                             \
        }                                                                              \
        asm volatile("cp.async.commit_group;\n" ::);                                   \
    }

    float acc[4][NF][4];
    #pragma unroll
    for (int i = 0; i < 4; i++)
        #pragma unroll
        for (int j = 0; j < NF; j++)
            #pragma unroll
            for (int q = 0; q < 4; q++) acc[i][j][q] = 0.f;

    const int NT = K / 16;
    GM_ISSUE(0, 0);
    GM_ISSUE(16, 1);
    GM_ISSUE(32, 2);

    for (int kt = 0; kt < NT; kt++) {
        const int slot = kt & 3;
        if (kt + 3 < NT) {
            asm volatile("cp.async.wait_group 2;\n" ::);
            __syncthreads();
            GM_ISSUE((kt + 3) * 16, (kt + 3) & 3);
        } else {
            asm volatile("cp.async.wait_group 0;\n" ::);
            __syncthreads();
        }

        const uint32_t abase = asb + (uint32_t)(slot * ABUFW) * 4u;
        const uint32_t* Bb = Bsb + slot * BBUFW;

        #pragma unroll
        for (int kk = 0; kk < 16; kk += 8) {
            uint32_t af[4][4], bf[NF][2];
            #pragma unroll
            for (int mf = 0; mf < 4; mf++) {
                const uint32_t sa = abase +
                    (uint32_t)(((wm * 64 + mf * 16 + arow) * AST + kk + acol) * 4);
                ldsm_x4(af[mf][0], af[mf][1], af[mf][2], af[mf][3], sa);
            }
            #pragma unroll
            for (int nf = 0; nf < NF; nf++) {
                const int cb = wn * WN + nf * 8 + g;
                bf[nf][0] = Bb[(kk + tg)     * BST + cb];
                bf[nf][1] = Bb[(kk + tg + 4) * BST + cb];
            }
            #pragma unroll
            for (int mf = 0; mf < 4; mf++)
                #pragma unroll
                for (int nf = 0; nf < NF; nf++)
                    mma_tf32(acc[mf][nf], af[mf], bf[nf]);
        }
    }

    #pragma unroll
    for (int mf = 0; mf < 4; mf++) {
        const int r0 = m0 + wm * 64 + mf * 16 + g;
        const int r1 = r0 + 8;
        #pragma unroll
        for (int nf = 0; nf < NF; nf++) {
            const int cc = n0 + wn * WN + nf * 8 + tg * 2;
            float b0 = 0.f, b1 = 0.f;
            if (bias) { b0 = bias[cc]; b1 = bias[cc + 1]; }
            if (r0 < M) {
                float v0 = acc[mf][nf][0] + b0;
                float v1 = acc[mf][nf][1] + b1;
                if (resid) {
                    v0 += resid[(long)r0 * ldc + cc];
                    v1 += resid[(long)r0 * ldc + cc + 1];
                }
                if (OB) *(uint32_t*)((__nv_bfloat16*)Cv + (long)r0 * ldc + cc) = packbf(v0, v1);
                else    *(float2*)((float*)Cv + (long)r0 * ldc + cc) = make_float2(v0, v1);
            }
            if (r1 < M) {
                float v0 = acc[mf][nf][2] + b0;
                float v1 = acc[mf][nf][3] + b1;
                if (resid) {
                    v0 += resid[(long)r1 * ldc + cc];
                    v1 += resid[(long)r1 * ldc + cc + 1];
                }
                if (OB) *(uint32_t*)((__nv_bfloat16*)Cv + (long)r1 * ldc + cc) = packbf(v0, v1);
                else    *(float2*)((float*)Cv + (long)r1 * ldc + cc) = make_float2(v0, v1);
            }
        }
    }
}

#define GSM_128_64 ((4 * 128 * AST + 4 * 16 * (256 + 4)) * 4)   // 107520
#define GSM_64_16  ((4 * 64 * AST + 4 * 16 * (128 + 4)) * 4)    // 54272

// ---------------------------------------------------------------------------
// bf16 flash attention; 3-stage cp.async pipeline.
// ---------------------------------------------------------------------------
#define FKST 88
#define FSTG 22528
#define FSM3 (3 * FSTG)

__global__ void __launch_bounds__(256, 2)
flash_bf_k(const __nv_bfloat16* __restrict__ Q, const __nv_bfloat16* __restrict__ K,
           const __nv_bfloat16* __restrict__ V, float* __restrict__ O)
{
    extern __shared__ char fsmc[];
    const uint32_t sb = (uint32_t)__cvta_generic_to_shared(fsmc);

    const int tid  = threadIdx.x;
    const int wid  = tid >> 5;
    const int lane = tid & 31;
    const int g    = lane >> 2;
    const int tg   = lane & 3;
    const int bh   = blockIdx.y;
    const int b    = bh / HH, h = bh % HH;
    const int row0 = blockIdx.x * 128;
    const int NT   = NN_ / 64;

    const __nv_bfloat16* Qp = Q + (long)(b * NN_ + row0) * DD + h * DH;
    const __nv_bfloat16* Kp = K + (long)b * NN_ * DD + h * DH;
    const __nv_bfloat16* Vp = V + (long)b * NN_ * DD + h * DH;
    float* Op = O + (long)(b * NN_ + row0) * DD + h * DH;

    const int krow = (lane & 7) + ((lane >> 4) << 3);
    const int kseg = ((lane >> 3) & 1) * 16;
    const int vrow = lane & 15;
    const int vseg = lane >> 4;

    uint32_t qa[5][4];
    {
        const __nv_bfloat16* q0 = Qp + (long)(wid * 16 + g) * DD;
        const __nv_bfloat16* q1 = q0 + 8 * DD;
        #pragma unroll
        for (int kc = 0; kc < 5; kc++) {
            const int c = kc * 16 + 2 * tg;
            qa[kc][0] = *(const uint32_t*)(q0 + c);
            qa[kc][1] = *(const uint32_t*)(q1 + c);
            qa[kc][2] = *(const uint32_t*)(q0 + c + 8);
            qa[kc][3] = *(const uint32_t*)(q1 + c + 8);
        }
    }

    float oa[10][4];
    #pragma unroll
    for (int nf = 0; nf < 10; nf++)
        #pragma unroll
        for (int q = 0; q < 4; q++) oa[nf][q] = 0.f;
    float mr0 = -1e30f, mr1 = -1e30f, lr0 = 0.f, lr1 = 0.f;

    #define FB_ISSUE(kt, slot)                                                         \
    {                                                                                   \
        for (int i = tid; i < 640; i += 256) {                                          \
            const int r = i / 10, c = i % 10;                                           \
            cp16(sb + (uint32_t)((slot) * FSTG + r * (FKST * 2) + c * 16),              \
                 Kp + (long)((kt) * 64 + r) * DD + c * 8);                              \
        }                                                                               \
        for (int i = tid; i < 640; i += 256) {                                          \
            const int r = i / 10, c = i % 10;                                           \
            cp16(sb + (uint32_t)((slot) * FSTG + 11264 + r * (FKST * 2) + c * 16),      \
                 Vp + (long)((kt) * 64 + r) * DD + c * 8);                              \
        }                                                                               \
        asm volatile("cp.async.commit_group;\n" ::);                                    \
    }

    FB_ISSUE(0, 0);
    FB_ISSUE(1, 1);
    int s0 = 0;

    for (int kt = 0; kt < NT; kt++) {
        if (kt + 2 < NT) {
            asm volatile("cp.async.wait_group 1;\n" ::);
            __syncthreads();
            int sn = s0 + 2; if (sn >= 3) sn -= 3;
            FB_ISSUE(kt + 2, sn);
        } else {
            asm volatile("cp.async.wait_group 0;\n" ::);
            __syncthreads();
        }

        const uint32_t kbase = sb + (uint32_t)(s0 * FSTG);
        const uint32_t vbase = kbase + 11264;

        float sa[8][4];
        #pragma unroll
        for (int nf = 0; nf < 8; nf++)
            #pragma unroll
            for (int q = 0; q < 4; q++) sa[nf][q] = 0.f;

        #pragma unroll
        for (int kc = 0; kc < 5; kc++) {
            #pragma unroll
            for (int nfp = 0; nfp < 4; nfp++) {
                uint32_t b0, b1, b2, b3;
                ldsm_x4(b0, b1, b2, b3,
                        kbase + (uint32_t)((nfp * 16 + krow) * (FKST * 2) + kc * 32 + kseg));
                uint32_t ba[2] = {b0, b1};
                uint32_t bb[2] = {b2, b3};
                mma_bf16(sa[2 * nfp],     qa[kc], ba);
                mma_bf16(sa[2 * nfp + 1], qa[kc], bb);
            }
        }

        float rm0 = -1e30f, rm1 = -1e30f;
        #pragma unroll
        for (int nf = 0; nf < 8; nf++) {
            rm0 = fmaxf(rm0, fmaxf(sa[nf][0], sa[nf][1]));
            rm1 = fmaxf(rm1, fmaxf(sa[nf][2], sa[nf][3]));
        }
        rm0 *= SCALE_ATTN; rm1 *= SCALE_ATTN;
        rm0 = fmaxf(rm0, __shfl_xor_sync(0xffffffffu, rm0, 1));
        rm0 = fmaxf(rm0, __shfl_xor_sync(0xffffffffu, rm0, 2));
        rm1 = fmaxf(rm1, __shfl_xor_sync(0xffffffffu, rm1, 1));
        rm1 = fmaxf(rm1, __shfl_xor_sync(0xffffffffu, rm1, 2));

        const float mn0 = fmaxf(mr0, rm0);
        const float mn1 = fmaxf(mr1, rm1);
        const float cr0 = __expf(mr0 - mn0);
        const float cr1 = __expf(mr1 - mn1);

        uint32_t pa[4][4];
        float rs0 = 0.f, rs1 = 0.f;
        #pragma unroll
        for (int nf = 0; nf < 8; nf++) {
            float p00 = __expf(sa[nf][0] * SCALE_ATTN - mn0);
            float p01 = __expf(sa[nf][1] * SCALE_ATTN - mn0);
            float p10 = __expf(sa[nf][2] * SCALE_ATTN - mn1);
            float p11 = __expf(sa[nf][3] * SCALE_ATTN - mn1);
            rs0 += p00 + p01;
            rs1 += p10 + p11;
            const int kc = nf >> 1, hi = (nf & 1) ? 2 : 0;
            pa[kc][hi]     = packbf(p00, p01);
            pa[kc][hi + 1] = packbf(p10, p11);
        }
        rs0 += __shfl_xor_sync(0xffffffffu, rs0, 1);
        rs0 += __shfl_xor_sync(0xffffffffu, rs0, 2);
        rs1 += __shfl_xor_sync(0xffffffffu, rs1, 1);
        rs1 += __shfl_xor_sync(0xffffffffu, rs1, 2);

        lr0 = lr0 * cr0 + rs0;  mr0 = mn0;
        lr1 = lr1 * cr1 + rs1;  mr1 = mn1;

        #pragma unroll
        for (int nf = 0; nf < 10; nf++) {
            oa[nf][0] *= cr0; oa[nf][1] *= cr0;
            oa[nf][2] *= cr1; oa[nf][3] *= cr1;
        }

        #pragma unroll
        for (int kc = 0; kc < 4; kc++) {
            #pragma unroll
            for (int nfp = 0; nfp < 5; nfp++) {
                uint32_t b0, b1, b2, b3;
                ldsm_x4_t(b0, b1, b2, b3,
                          vbase + (uint32_t)((kc * 16 + vrow) * (FKST * 2)
                                             + (nfp * 2 + vseg) * 16));
                uint32_t ba[2] = {b0, b1};
                uint32_t bb[2] = {b2, b3};
                mma_bf16(oa[2 * nfp],     pa[kc], ba);
                mma_bf16(oa[2 * nfp + 1], pa[kc], bb);
            }
        }

        s0 = (s0 == 2) ? 0 : s0 + 1;
    }

    const float inv0 = 1.f / lr0;
    const float inv1 = 1.f / lr1;
    #pragma unroll
    for (int nf = 0; nf < 10; nf++) {
        const int cc = nf * 8 + tg * 2;
        *(float2*)(Op + (long)(wid * 16 + g)     * DD + cc) =
            make_float2(oa[nf][0] * inv0, oa[nf][1] * inv0);
        *(float2*)(Op + (long)(wid * 16 + g + 8) * DD + cc) =
            make_float2(oa[nf][2] * inv1, oa[nf][3] * inv1);
    }
}

// ---------------- LayerNorm -------------------------------------------------
__global__ __launch_bounds__(256)
void ln_k(const float* __restrict__ x, const float* __restrict__ w,
          const float* __restrict__ b, float* __restrict__ out)
{
    const int lane = threadIdx.x & 31;
    const long row = (long)blockIdx.x * 8 + (threadIdx.x >> 5);
    const float4* p = (const float4*)(x + row * DD);

    float4 v[5];
    float s = 0.f, ss = 0.f;
    #pragma unroll
    for (int i = 0; i < 5; i++) {
        v[i] = p[i * 32 + lane];
        s  += v[i].x + v[i].y + v[i].z + v[i].w;
        ss += v[i].x * v[i].x + v[i].y * v[i].y + v[i].z * v[i].z + v[i].w * v[i].w;
    }
    #pragma unroll
    for (int o = 16; o > 0; o >>= 1) {
        s  += __shfl_xor_sync(0xffffffffu, s,  o);
        ss += __shfl_xor_sync(0xffffffffu, ss, o);
    }
    const float mean = s * (1.f / DD);
    const float var  = ss * (1.f / DD) - mean * mean;
    const float inv  = rsqrtf(var + EPS_);

    float4* o4 = (float4*)(out + row * DD);
    const float4* w4 = (const float4*)w;
    const float4* b4 = (const float4*)b;
    #pragma unroll
    for (int i = 0; i < 5; i++) {
        const int c = i * 32 + lane;
        float4 wv = w4[c], bv = b4[c], r;
        r.x = (v[i].x - mean) * inv * wv.x + bv.x;
        r.y = (v[i].y - mean) * inv * wv.y + bv.y;
        r.z = (v[i].z - mean) * inv * wv.z + bv.z;
        r.w = (v[i].w - mean) * inv * wv.w + bv.w;
        o4[c] = r;
    }
}

// ---------------- cross-attention -------------------------------------------
#define XSMEM_BYTES 54720

__global__ __launch_bounds__(256)
void xattn_k(const float* __restrict__ Q, const float* __restrict__ K,
             const float* __restrict__ V, float* __restrict__ O)
{
    extern __shared__ float xs[];
    float* Ks = xs;
    float* Vs = xs + 6240;
    float* sc = xs + 12400;
    float* qb = xs + 13040;

    const int tid  = threadIdx.x;
    const int wid  = tid >> 5;
    const int lane = tid & 31;
    const int bh   = blockIdx.y;
    const int b    = bh / HH, h = bh % HH;
    const int q0   = blockIdx.x * 128;

    const float* Kp = K + (long)b * CN_ * DD + h * DH;
    const float* Vp = V + (long)b * CN_ * DD + h * DH;
    for (int idx = tid; idx < CN_ * DH; idx += 256) {
        const int j = idx / DH, d = idx % DH;
        Ks[j * 81 + d] = Kp[(long)j * DD + d];
        Vs[j * 80 + d] = Vp[(long)j * DD + d];
    }
    __syncthreads();

    float* scw = sc + wid * 80;
    float* qbw = qb + wid * 80;

    for (int qq = wid; qq < 128; qq += 8) {
        const int qrow = q0 + qq;
        const float* qp = Q + ((long)(b * NN_ + qrow) * DD + h * DH);
        for (int d = lane; d < DH; d += 32) qbw[d] = qp[d];
        __syncwarp();

        float mx = -1e30f;
        for (int j = lane; j < CN_; j += 32) {
            float s = 0.f;
            #pragma unroll 8
            for (int d = 0; d < DH; d++) s += qbw[d] * Ks[j * 81 + d];
            s *= SCALE_ATTN;
            scw[j] = s;
            mx = fmaxf(mx, s);
        }
        #pragma unroll
        for (int o = 16; o > 0; o >>= 1)
            mx = fmaxf(mx, __shfl_xor_sync(0xffffffffu, mx, o));

        float sum = 0.f;
        __syncwarp();
        for (int j = lane; j < CN_; j += 32) {
            float e = __expf(scw[j] - mx);
            scw[j] = e;
            sum += e;
        }
        #pragma unroll
        for (int o = 16; o > 0; o >>= 1)
            sum += __shfl_xor_sync(0xffffffffu, sum, o);
        const float inv = 1.f / sum;
        __syncwarp();

        float* op = O + ((long)(b * NN_ + qrow) * DD + h * DH);
        for (int d = lane; d < DH; d += 32) {
            float acc = 0.f;
            #pragma unroll 7
            for (int j = 0; j < CN_; j++) acc += scw[j] * Vs[j * 80 + d];
            op[d] = acc * inv;
        }
        __syncwarp();
    }
}

// ---------------- GEGLU -----------------------------------------------------
__device__ __forceinline__ float gelu1(float g) {
    return 0.5f * g * (1.f + erff(g * 0.70710678118654752f));
}

__global__ __launch_bounds__(256)
void geglu_k(const float4* __restrict__ proj, float4* __restrict__ out)
{
    const long idx = (long)blockIdx.x * 256 + threadIdx.x;
    const long row = idx / (FF_ / 4);
    const long c   = idx % (FF_ / 4);
    const float4 a = proj[row * (2 * FF_ / 4) + c];
    const float4 g = proj[row * (2 * FF_ / 4) + FF_ / 4 + c];
    float4 r;
    r.x = a.x * gelu1(g.x);
    r.y = a.y * gelu1(g.y);
    r.z = a.z * gelu1(g.z);
    r.w = a.w * gelu1(g.w);
    out[idx] = r;
}

// ---------------- host ------------------------------------------------------
// N=640 single gemm: M64 tiles, 3 CTAs/SM.
static inline void gemm_640(const float* A, const float* B, float* C,
                            int M, int K, const float* bias, const float* resid)
{
    dim3 grid(DD / 128, (M + 63) / 64);
    gemm_mma_k<64, 16, false><<<grid, 256, GSM_64_16>>>(
        A, B, C, M, DD, K, K, DD, DD, bias, resid,
        nullptr, nullptr, nullptr, nullptr);
}

extern "C" void kernel_launch(void* const* d_in, const int* in_sizes, int n_in,
                              void* d_out, int out_size)
{
    const float* x    = (const float*)d_in[0];
    const float* ctx  = (const float*)d_in[1];
    const float* ln1w = (const float*)d_in[2];
    const float* ln1b = (const float*)d_in[3];
    const float* ln2w = (const float*)d_in[4];
    const float* ln2b = (const float*)d_in[5];
    const float* ln3w = (const float*)d_in[6];
    const float* ln3b = (const float*)d_in[7];
    const float* wq1  = (const float*)d_in[8];
    const float* wk1  = (const float*)d_in[9];
    const float* wv1  = (const float*)d_in[10];
    const float* wo1  = (const float*)d_in[11];
    const float* bo1  = (const float*)d_in[12];
    const float* wq2  = (const float*)d_in[13];
    const float* wk2  = (const float*)d_in[14];
    const float* wv2  = (const float*)d_in[15];
    const float* wo2  = (const float*)d_in[16];
    const float* bo2  = (const float*)d_in[17];
    const float* wff1 = (const float*)d_in[18];
    const float* bff1 = (const float*)d_in[19];
    const float* wff2 = (const float*)d_in[20];
    const float* bff2 = (const float*)d_in[21];
    float* out = (float*)d_out;

    float *xp, *hp, *qp, *kp, *vp, *ap, *pp, *fp;
    __nv_bfloat16 *qb, *kb, *vb;
    cudaGetSymbolAddress((void**)&xp, g_x);
    cudaGetSymbolAddress((void**)&hp, g_h);
    cudaGetSymbolAddress((void**)&qp, g_q);
    cudaGetSymbolAddress((void**)&kp, g_k);
    cudaGetSymbolAddress((void**)&vp, g_v);
    cudaGetSymbolAddress((void**)&ap, g_attn);
    cudaGetSymbolAddress((void**)&pp, g_proj);
    cudaGetSymbolAddress((void**)&fp, g_ffh);
    cudaGetSymbolAddress((void**)&qb, g_qb);
    cudaGetSymbolAddress((void**)&kb, g_kb);
    cudaGetSymbolAddress((void**)&vb, g_vb);

    cudaFuncSetAttribute(gemm_mma_k<128, 64, false>,
                         cudaFuncAttributeMaxDynamicSharedMemorySize, GSM_128_64);
    cudaFuncSetAttribute(gemm_mma_k<64, 16, false>,
                         cudaFuncAttributeMaxDynamicSharedMemorySize, GSM_64_16);
    cudaFuncSetAttribute(gemm_mma_k<64, 16, true>,
                         cudaFuncAttributeMaxDynamicSharedMemorySize, GSM_64_16);
    cudaFuncSetAttribute(flash_bf_k, cudaFuncAttributeMaxDynamicSharedMemorySize, FSM3);
    cudaFuncSetAttribute(xattn_k,    cudaFuncAttributeMaxDynamicSharedMemorySize, XSMEM_BYTES);

    const int M = BB * NN_;
    cudaMemcpyAsync(xp, x, (long)M * DD * sizeof(float), cudaMemcpyDeviceToDevice);

    // ===== self-attention =====
    ln_k<<<M / 8, 256>>>(xp, ln1w, ln1b, hp);
    {   // QKV batched: z in {0,1,2} -> (wq1,qb), (wk1,kb), (wv1,vb); bf16 out
        dim3 grid(DD / 128, M / 64, 3);
        gemm_mma_k<64, 16, true><<<grid, 256, GSM_64_16>>>(
            hp, wq1, qb, M, DD, DD, DD, DD, DD, nullptr, nullptr,
            wk1, kb, wv1, vb);
    }
    {
        dim3 grid(NN_ / 128, BB * HH);
        flash_bf_k<<<grid, 256, FSM3>>>(qb, kb, vb, ap);
    }
    gemm_640(ap, wo1, xp, M, DD, bo1, xp);

    // ===== cross-attention =====
    ln_k<<<M / 8, 256>>>(xp, ln2w, ln2b, hp);
    gemm_640(hp, wq2, qp, M, DD, nullptr, nullptr);
    {   // wk2 / wv2 batched (z in {0,1}), M=154, K=768
        dim3 grid(DD / 128, (BB * CN_ + 63) / 64, 2);
        gemm_mma_k<64, 16, false><<<grid, 256, GSM_64_16>>>(
            ctx, wk2, kp, BB * CN_, DD, CDIM, CDIM, DD, DD, nullptr, nullptr,
            wv2, vp, nullptr, nullptr);
    }
    {
        dim3 grid(NN_ / 128, BB * HH);
        xattn_k<<<grid, 256, XSMEM_BYTES>>>(qp, kp, vp, ap);
    }
    gemm_640(ap, wo2, xp, M, DD, bo2, xp);

    // ===== GEGLU FF =====
    ln_k<<<M / 8, 256>>>(xp, ln3w, ln3b, hp);
    {   // FF1: N=5120, keep 128x256 tiles
        dim3 grid(2 * FF_ / 256, M / 128);
        gemm_mma_k<128, 64, false><<<grid, 256, GSM_128_64>>>(
            hp, wff1, pp, M, 2 * FF_, DD, DD, 2 * FF_, 2 * FF_, bff1, nullptr,
            nullptr, nullptr, nullptr, nullptr);
    }
    geglu_k<<<(int)(((long)M * (FF_ / 4)) / 256), 256>>>((const float4*)pp, (float4*)fp);
    gemm_640(fp, wff2, out, M, FF_, bff2, xp);
}